// round 8
// baseline (speedup 1.0000x reference)
#include <cuda_runtime.h>
#include <math.h>

#define NU 200000
#define NI 200000
#define D  128
#define B  4096
#define KRNN 264   // [x(129) | h(128) | pad(7)] ; 264 = 33*8

// ---- output layout (flattened tuple, row-major) ----
#define OFF_PRED       0
#define OFF_TARGET     (B*2*D)
#define OFF_UPD_USER   (OFF_TARGET + B*2*D)
#define OFF_USER_EMB   (OFF_UPD_USER + B*D)
#define OFF_UPD_ITEM   (OFF_USER_EMB + B*D)
#define OFF_ITEM_EMB   (OFF_UPD_ITEM + B*D)
#define OFF_DYN_USER   (OFF_ITEM_EMB + B*D)
#define OFF_DYN_ITEM   (OFF_DYN_USER + NU*D)
#define OFF_ISNEW_U    (OFF_DYN_ITEM + NI*D)
#define OFF_ISNEW_I    (OFF_ISNEW_U + NU)

// ---- device scratch ----
__device__ __align__(16) float g_Xpred[B * 512];
__device__ __align__(16) float g_Xu[B * KRNN];
__device__ __align__(16) float g_Xi[B * KRNN];
__device__ __align__(16) float g_Wu[D * KRNN];
__device__ __align__(16) float g_Wi[D * KRNN];
__device__ float g_bu[D];
__device__ float g_bi[D];
// winner sentinel: 0 = none, else b+1. Zero-init at load; scatter_kernel
// resets every entry it consumed, so each graph replay starts from all-zero.
__device__ int g_winner_u[NU];
__device__ int g_winner_i[NI];

typedef unsigned long long ull;
#define FFMA2(c, a, b) asm("fma.rn.f32x2 %0, %1, %2, %3;" \
    : "=l"(c) : "l"(a), "l"(b), "l"(c))
#define PACK2(d, x, y) asm("mov.b64 %0, {%1, %2};" : "=l"(d) : "f"(x), "f"(y))
#define UNPACK2(lo, hi, v) asm("mov.b64 {%0, %1}, %2;" : "=f"(lo), "=f"(hi) : "l"(v))

// ---- copy partitioning (in float4 units) ----
#define N4_U    (NU * D / 4)     // 6.4M
#define N4_I    (NI * D / 4)     // 6.4M
#define N4_ISU  (NU / 4)         // 50K
#define N4_ISI  (NI / 4)         // 50K
// phase1 copies ALL of dynU + dynI[0, C1_DYNI); phase2 copies the rest
// (sized so phase2 copy ~ GEMM duration; both phases DRAM-saturated)
#define C1_DYNI 1700000

#define P1_COPY 1536             // copy CTAs in phase1
#define P2_COPY 1024             // copy CTAs in phase2

// MLP=8 ranged copy: CTAs {cta in [0,ncta)} copy src[lo,hi) -> dst[lo,hi)
__device__ __forceinline__ void copy_range(const float4* __restrict__ src,
                                           float4* __restrict__ dst,
                                           int lo, int hi, int cta, int ncta) {
    int stride = ncta * 128;
    int i = lo + cta * 128 + (int)threadIdx.x;
    for (; i + 7 * stride < hi; i += 8 * stride) {
        float4 v0 = src[i];
        float4 v1 = src[i + stride];
        float4 v2 = src[i + 2 * stride];
        float4 v3 = src[i + 3 * stride];
        float4 v4 = src[i + 4 * stride];
        float4 v5 = src[i + 5 * stride];
        float4 v6 = src[i + 6 * stride];
        float4 v7 = src[i + 7 * stride];
        dst[i]              = v0;
        dst[i + stride]     = v1;
        dst[i + 2 * stride] = v2;
        dst[i + 3 * stride] = v3;
        dst[i + 4 * stride] = v4;
        dst[i + 5 * stride] = v5;
        dst[i + 6 * stride] = v6;
        dst[i + 7 * stride] = v7;
    }
    for (; i < hi; i += stride) dst[i] = src[i];
}

// ---------------------------------------------------------------------------
// phase1: [copy bulk | gather | winner | prep] fused in one launch
__global__ void __launch_bounds__(128) phase1_kernel(
        const int* __restrict__ uid, const int* __restrict__ pid,
        const int* __restrict__ iid,
        const float* __restrict__ t_item, const float* __restrict__ t_user,
        const float* __restrict__ dynU, const float* __restrict__ dynI,
        const float* __restrict__ isU, const float* __restrict__ isI,
        const float* __restrict__ statU, const float* __restrict__ statI,
        const float* __restrict__ initU, const float* __restrict__ initI,
        const float* __restrict__ tdW, const float* __restrict__ tdb,
        const float* __restrict__ uWih, const float* __restrict__ uWhh,
        const float* __restrict__ ubih, const float* __restrict__ ubhh,
        const float* __restrict__ iWih, const float* __restrict__ iWhh,
        const float* __restrict__ ibih, const float* __restrict__ ibhh,
        float* __restrict__ out) {
    int bx = blockIdx.x;

    if (bx < P1_COPY) {
        // is_new flags + ALL of dynU + first chunk of dynI
        copy_range((const float4*)isU, (float4*)(out + OFF_ISNEW_U),
                   0, N4_ISU, bx, P1_COPY);
        copy_range((const float4*)isI, (float4*)(out + OFF_ISNEW_I),
                   0, N4_ISI, bx, P1_COPY);
        copy_range((const float4*)dynU, (float4*)(out + OFF_DYN_USER),
                   0, N4_U, bx, P1_COPY);
        copy_range((const float4*)dynI, (float4*)(out + OFF_DYN_ITEM),
                   0, C1_DYNI, bx, P1_COPY);
        return;
    }
    bx -= P1_COPY;

    if (bx < B) {
        // ---- gather: one block per batch row ----
        int b = bx;
        int d = threadIdx.x;           // 0..127
        int u = uid[b], p = pid[b], it = iid[b];
        float ti = t_item[b], tu = t_user[b];
        float fu = isU[u], fi = isI[it], fp = isI[p];

        float ue = fu * initU[d] + dynU[(long)u * D + d];
        float ie = fi * initI[d] + dynI[(long)it * D + d];
        float pe = fp * initI[d] + dynI[(long)p * D + d];
        float su = statU[(long)u * D + d];
        float si = statI[(long)it * D + d];
        float ps = statI[(long)p * D + d];

        out[OFF_USER_EMB + b * D + d] = ue;
        out[OFF_ITEM_EMB + b * D + d] = ie;
        out[OFF_TARGET + b * 2 * D + d]     = ie;
        out[OFF_TARGET + b * 2 * D + D + d] = si;

        float proj = ue * (1.f + ti * tdW[d] + tdb[d]);
        g_Xpred[b * 512 + d]       = proj;
        g_Xpred[b * 512 + 128 + d] = pe;
        g_Xpred[b * 512 + 256 + d] = ps;
        g_Xpred[b * 512 + 384 + d] = su;

        g_Xu[b * KRNN + d]       = ie;
        g_Xu[b * KRNN + 129 + d] = ue;
        g_Xi[b * KRNN + d]       = ue;
        g_Xi[b * KRNN + 129 + d] = ie;
        if (d == 0) {
            g_Xu[b * KRNN + 128] = ti;
            g_Xi[b * KRNN + 128] = tu;
        }
        if (d < KRNN - 257) {
            g_Xu[b * KRNN + 257 + d] = 0.f;
            g_Xi[b * KRNN + 257 + d] = 0.f;
        }
        return;
    }
    bx -= B;

    if (bx < B / 128) {
        // ---- winner: last occurrence wins; sentinel b+1 over zero-init ----
        int b = bx * 128 + threadIdx.x;
        atomicMax(&g_winner_u[uid[b]], b + 1);
        atomicMax(&g_winner_i[iid[b]], b + 1);
        return;
    }
    bx -= B / 128;

    {
        // ---- prep: combined RNN weights [Wih | Whh | 0] + fused biases ----
        int i = bx * 128 + threadIdx.x;
        if (i < D * KRNN) {
            int n = i / KRNN, k = i % KRNN;
            float wu, wi;
            if (k < 129)      { wu = uWih[n * 129 + k];       wi = iWih[n * 129 + k]; }
            else if (k < 257) { wu = uWhh[n * 128 + (k-129)]; wi = iWhh[n * 128 + (k-129)]; }
            else              { wu = 0.f; wi = 0.f; }
            g_Wu[i] = wu; g_Wi[i] = wi;
        }
        if (i < D) { g_bu[i] = ubih[i] + ubhh[i]; g_bi[i] = ibih[i] + ibhh[i]; }
    }
}
#define P1_GRID (P1_COPY + B + B/128 + (D*KRNN + 127)/128)

// ---------------------------------------------------------------------------
// C[m][n] = act( sum_k X[m][k]*W[n][k] + bias[n] )
// tile 64(M) x 64(N), BK=8, 128 threads, 8x4 microtile (M as 4 f32x2 pairs)
template <int KDIM, bool TANH>
__device__ __forceinline__ void gemm64_body(int m0, int n0,
                                            const float* __restrict__ X,
                                            const float* __restrict__ W,
                                            const float* __restrict__ bias,
                                            float* __restrict__ C, int ldc) {
    __shared__ __align__(16) float As[2][8][64];
    __shared__ __align__(16) float Bs[2][8][64];
    int tid = threadIdx.x;       // 0..127
    int tx = tid & 15;           // N dir (x4)
    int ty = tid >> 4;           // M dir (x8 = 4 f32x2 pairs)

    ull acc[4][4];
    #pragma unroll
    for (int i = 0; i < 4; i++)
        #pragma unroll
        for (int j = 0; j < 4; j++) acc[i][j] = 0ull;

    int lrow = tid >> 1;            // 0..63
    int lcol = (tid & 1) * 4;       // 0 or 4
    const float* srcA = X + (long)(m0 + lrow) * KDIM + lcol;
    const float* srcB = W + (long)(n0 + lrow) * KDIM + lcol;
    const int KT = KDIM / 8;

    float4 va = *(const float4*)srcA;
    float4 vb = *(const float4*)srcB;
    As[0][lcol + 0][lrow] = va.x; As[0][lcol + 1][lrow] = va.y;
    As[0][lcol + 2][lrow] = va.z; As[0][lcol + 3][lrow] = va.w;
    Bs[0][lcol + 0][lrow] = vb.x; Bs[0][lcol + 1][lrow] = vb.y;
    Bs[0][lcol + 2][lrow] = vb.z; Bs[0][lcol + 3][lrow] = vb.w;
    __syncthreads();

    int buf = 0;
    for (int kt = 0; kt < KT; kt++) {
        if (kt + 1 < KT) {
            va = *(const float4*)(srcA + (kt + 1) * 8);
            vb = *(const float4*)(srcB + (kt + 1) * 8);
        }
        #pragma unroll
        for (int k = 0; k < 8; k++) {
            ulonglong2 a01 = *(const ulonglong2*)&As[buf][k][ty * 8];
            ulonglong2 a23 = *(const ulonglong2*)&As[buf][k][ty * 8 + 4];
            float4 b0 = *(const float4*)&Bs[buf][k][tx * 4];
            ull bb[4];
            PACK2(bb[0], b0.x, b0.x); PACK2(bb[1], b0.y, b0.y);
            PACK2(bb[2], b0.z, b0.z); PACK2(bb[3], b0.w, b0.w);
            #pragma unroll
            for (int j = 0; j < 4; j++) {
                FFMA2(acc[0][j], a01.x, bb[j]);
                FFMA2(acc[1][j], a01.y, bb[j]);
                FFMA2(acc[2][j], a23.x, bb[j]);
                FFMA2(acc[3][j], a23.y, bb[j]);
            }
        }
        if (kt + 1 < KT) {
            buf ^= 1;
            As[buf][lcol + 0][lrow] = va.x; As[buf][lcol + 1][lrow] = va.y;
            As[buf][lcol + 2][lrow] = va.z; As[buf][lcol + 3][lrow] = va.w;
            Bs[buf][lcol + 0][lrow] = vb.x; Bs[buf][lcol + 1][lrow] = vb.y;
            Bs[buf][lcol + 2][lrow] = vb.z; Bs[buf][lcol + 3][lrow] = vb.w;
            __syncthreads();
        }
    }

    float4 bias4 = *(const float4*)&bias[n0 + tx * 4];
    float bn[4] = {bias4.x, bias4.y, bias4.z, bias4.w};
    #pragma unroll
    for (int p = 0; p < 4; p++) {
        int mlo = m0 + ty * 8 + 2 * p;
        float lo[4], hi[4];
        #pragma unroll
        for (int j = 0; j < 4; j++) {
            float l, h;
            UNPACK2(l, h, acc[p][j]);
            l += bn[j]; h += bn[j];
            if (TANH) { l = tanhf(l); h = tanhf(h); }
            lo[j] = l; hi[j] = h;
        }
        *(float4*)&C[(long)mlo * ldc + n0 + tx * 4]       = make_float4(lo[0], lo[1], lo[2], lo[3]);
        *(float4*)&C[(long)(mlo + 1) * ldc + n0 + tx * 4] = make_float4(hi[0], hi[1], hi[2], hi[3]);
    }
}

// ---------------------------------------------------------------------------
// phase2: [pred GEMM | RNN GEMMs | copy remainder] fused in one launch
__global__ void __launch_bounds__(128) phase2_kernel(
        const float* __restrict__ dynI,
        const float* __restrict__ predW, const float* __restrict__ predb,
        float* __restrict__ out) {
    int bx = blockIdx.x;

    if (bx < 256) {
        // pred: 64 M-tiles x 4 N-tiles
        int m0 = (bx & 63) * 64;
        int n0 = (bx >> 6) * 64;
        gemm64_body<512, false>(m0, n0, g_Xpred, predW, predb, out + OFF_PRED, 256);
        return;
    }
    bx -= 256;

    if (bx < 256) {
        // RNN cells: 64 M-tiles x 2 N-tiles x 2 cells
        int cell = bx >> 7;
        int r = bx & 127;
        int m0 = (r & 63) * 64;
        int n0 = (r >> 6) * 64;
        if (cell == 0)
            gemm64_body<KRNN, true>(m0, n0, g_Xu, g_Wu, g_bu, out + OFF_UPD_USER, 128);
        else
            gemm64_body<KRNN, true>(m0, n0, g_Xi, g_Wi, g_bi, out + OFF_UPD_ITEM, 128);
        return;
    }
    bx -= 256;

    // copy remainder of dynI
    copy_range((const float4*)dynI, (float4*)(out + OFF_DYN_ITEM),
               C1_DYNI, N4_I, bx, P2_COPY);
}
#define P2_GRID (256 + 256 + P2_COPY)

// ---------------------------------------------------------------------------
// patch winner rows, zero is_new for batch ids, reset consumed winner entries
__global__ void scatter_kernel(const int* __restrict__ uid, const int* __restrict__ iid,
                               float* __restrict__ out) {
    int gw = blockIdx.x * 8 + (threadIdx.x >> 5);
    int lane = threadIdx.x & 31;
    if (gw < B) {
        int id = uid[gw];
        if (lane == 0) out[OFF_ISNEW_U + id] = 0.f;
        if (g_winner_u[id] == gw + 1) {
            float4 v = *(const float4*)(out + OFF_UPD_USER + (long)gw * D + lane * 4);
            *(float4*)(out + OFF_DYN_USER + (long)id * D + lane * 4) = v;
            if (lane == 0) g_winner_u[id] = 0;   // restore zero state for next replay
        }
    } else {
        int b = gw - B;
        if (b < B) {
            int id = iid[b];
            if (lane == 0) out[OFF_ISNEW_I + id] = 0.f;
            if (g_winner_i[id] == b + 1) {
                float4 v = *(const float4*)(out + OFF_UPD_ITEM + (long)b * D + lane * 4);
                *(float4*)(out + OFF_DYN_ITEM + (long)id * D + lane * 4) = v;
                if (lane == 0) g_winner_i[id] = 0;
            }
        }
    }
}

// ---------------------------------------------------------------------------
extern "C" void kernel_launch(void* const* d_in, const int* in_sizes, int n_in,
                              void* d_out, int out_size) {
    const int*   uid   = (const int*)d_in[0];
    const int*   pid   = (const int*)d_in[1];
    const int*   iid   = (const int*)d_in[2];
    const float* tItem = (const float*)d_in[3];
    const float* tUser = (const float*)d_in[4];
    const float* dynU  = (const float*)d_in[5];
    const float* dynI  = (const float*)d_in[6];
    const float* isU   = (const float*)d_in[7];
    const float* isI   = (const float*)d_in[8];
    const float* statU = (const float*)d_in[9];
    const float* statI = (const float*)d_in[10];
    const float* initU = (const float*)d_in[11];
    const float* initI = (const float*)d_in[12];
    const float* uWih  = (const float*)d_in[13];
    const float* uWhh  = (const float*)d_in[14];
    const float* ubih  = (const float*)d_in[15];
    const float* ubhh  = (const float*)d_in[16];
    const float* iWih  = (const float*)d_in[17];
    const float* iWhh  = (const float*)d_in[18];
    const float* ibih  = (const float*)d_in[19];
    const float* ibhh  = (const float*)d_in[20];
    const float* predW = (const float*)d_in[21];
    const float* predb = (const float*)d_in[22];
    const float* tdW   = (const float*)d_in[23];
    const float* tdb   = (const float*)d_in[24];
    float* out = (float*)d_out;

    phase1_kernel<<<P1_GRID, 128>>>(uid, pid, iid, tItem, tUser, dynU, dynI,
                                    isU, isI, statU, statI, initU, initI,
                                    tdW, tdb, uWih, uWhh, ubih, ubhh,
                                    iWih, iWhh, ibih, ibhh, out);
    phase2_kernel<<<P2_GRID, 128>>>(dynI, predW, predb, out);
    scatter_kernel<<<(2 * B) / 8, 256>>>(uid, iid, out);
}

// round 10
// speedup vs baseline: 1.0198x; 1.0198x over previous
#include <cuda_runtime.h>
#include <cuda_bf16.h>
#include <math.h>
#include <stdint.h>

#define NU 200000
#define NI 200000
#define D  128
#define B  4096
#define KP  512     // pred K
#define KFP 32      // pred K frags (K/16)
#define KR  272     // RNN K: [x(128) | h(128) | t(1) | pad(15)]
#define KFR 17      // RNN K frags

// ---- output layout (flattened tuple, row-major) ----
#define OFF_PRED       0
#define OFF_TARGET     (B*2*D)
#define OFF_UPD_USER   (OFF_TARGET + B*2*D)
#define OFF_USER_EMB   (OFF_UPD_USER + B*D)
#define OFF_UPD_ITEM   (OFF_USER_EMB + B*D)
#define OFF_ITEM_EMB   (OFF_UPD_ITEM + B*D)
#define OFF_DYN_USER   (OFF_ITEM_EMB + B*D)
#define OFF_DYN_ITEM   (OFF_DYN_USER + NU*D)
#define OFF_ISNEW_U    (OFF_DYN_ITEM + NI*D)
#define OFF_ISNEW_I    (OFF_ISNEW_U + NU)

typedef __nv_bfloat16 bf16;

// ---- device scratch: operands in m16n8k16 FRAGMENT layout, hi/lo bf16 ----
__device__ __align__(16) bf16 g_XpH[B * KP];
__device__ __align__(16) bf16 g_XpL[B * KP];
__device__ __align__(16) bf16 g_XuH[B * KR];
__device__ __align__(16) bf16 g_XuL[B * KR];
__device__ __align__(16) bf16 g_XiH[B * KR];
__device__ __align__(16) bf16 g_XiL[B * KR];
__device__ __align__(16) bf16 g_WpH[256 * KP];
__device__ __align__(16) bf16 g_WpL[256 * KP];
__device__ __align__(16) bf16 g_WuH[D * KR];
__device__ __align__(16) bf16 g_WuL[D * KR];
__device__ __align__(16) bf16 g_WvH[D * KR];
__device__ __align__(16) bf16 g_WvL[D * KR];
__device__ float g_bu[D];
__device__ float g_bi[D];
// winner sentinel: 0 = none, else b+1. Zero-init at load; scatter resets.
__device__ int g_winner_u[NU];
__device__ int g_winner_i[NI];

// m16n8k16 A-fragment offset (bf16 units) for even k (pair-aligned):
// subtile (mf,kf) is 256 bf16; lane g*4+t owns 16B slot = regs a0..a3
__device__ __forceinline__ int a_off(int m, int k0, int KF) {
    int mf = m >> 4, r = m & 15, g = r & 7, h = r >> 3;
    int kf = k0 >> 4, kl = k0 & 15, t = (kl >> 1) & 3, reg = h + 2 * (kl >> 3);
    return ((mf * KF + kf) << 8) + (((g << 2) + t) << 3) + reg * 2;
}
// B-fragment offset: subtile (nf,kf) is 128 bf16; lane g*4+t owns 8B slot
__device__ __forceinline__ int b_off(int n, int k0, int KF) {
    int nf = n >> 3, g = n & 7;
    int kf = k0 >> 4, kl = k0 & 15, t = (kl >> 1) & 3, reg = kl >> 3;
    return ((nf * KF + kf) << 7) + (((g << 2) + t) << 2) + reg * 2;
}

__device__ __forceinline__ void mma_bf16(float* c, uint4 a, uint2 b) {
    asm volatile(
        "mma.sync.aligned.m16n8k16.row.col.f32.bf16.bf16.f32 "
        "{%0,%1,%2,%3},{%4,%5,%6,%7},{%8,%9},{%0,%1,%2,%3};"
        : "+f"(c[0]), "+f"(c[1]), "+f"(c[2]), "+f"(c[3])
        : "r"(a.x), "r"(a.y), "r"(a.z), "r"(a.w), "r"(b.x), "r"(b.y));
}

// ---- copy machinery (proven saturated at MLP=8) ----
#define N4_U    (NU * D / 4)
#define N4_I    (NI * D / 4)
#define N4_ISU  (NU / 4)
#define N4_ISI  (NI / 4)
#define P1_COPY 1024
#define P2_COPY 1024

__device__ __forceinline__ void copy_range(const float4* __restrict__ src,
                                           float4* __restrict__ dst,
                                           int lo, int hi, int cta, int ncta) {
    int stride = ncta * 128;
    int i = lo + cta * 128 + (int)threadIdx.x;
    for (; i + 7 * stride < hi; i += 8 * stride) {
        float4 v0 = src[i];
        float4 v1 = src[i + stride];
        float4 v2 = src[i + 2 * stride];
        float4 v3 = src[i + 3 * stride];
        float4 v4 = src[i + 4 * stride];
        float4 v5 = src[i + 5 * stride];
        float4 v6 = src[i + 6 * stride];
        float4 v7 = src[i + 7 * stride];
        dst[i]              = v0; dst[i + stride]     = v1;
        dst[i + 2 * stride] = v2; dst[i + 3 * stride] = v3;
        dst[i + 4 * stride] = v4; dst[i + 5 * stride] = v5;
        dst[i + 6 * stride] = v6; dst[i + 7 * stride] = v7;
    }
    for (; i < hi; i += stride) dst[i] = src[i];
}

// split v into hi/lo bf16, pack with lane-partner (d^1) and store pair (even d)
__device__ __forceinline__ void frag_pair_A(bf16* Hd, bf16* Ld, int m, int kbase,
                                            int d, int KF, float v) {
    bf16 h = __float2bfloat16(v);
    bf16 l = __float2bfloat16(v - __bfloat162float(h));
    uint32_t hu = __bfloat16_as_ushort(h), lu = __bfloat16_as_ushort(l);
    uint32_t ph = __shfl_xor_sync(0xffffffffu, hu, 1);
    uint32_t pl = __shfl_xor_sync(0xffffffffu, lu, 1);
    if (!(d & 1)) {
        int off = a_off(m, kbase + d, KF);
        *(uint32_t*)(Hd + off) = hu | (ph << 16);
        *(uint32_t*)(Ld + off) = lu | (pl << 16);
    }
}

// ---------------------------------------------------------------------------
// phase1: [copy dynU+flags | gather (frag-layout X) | winner | prep (frag W)]
#define PREP_PRED 512        // 65536 pred-W pairs / 128
#define PREP_RNN  137        // 17408 rnn pairs / 128 + bias block
__global__ void __launch_bounds__(128) phase1_kernel(
        const int* __restrict__ uid, const int* __restrict__ pid,
        const int* __restrict__ iid,
        const float* __restrict__ t_item, const float* __restrict__ t_user,
        const float* __restrict__ dynU, const float* __restrict__ dynI,
        const float* __restrict__ isU, const float* __restrict__ isI,
        const float* __restrict__ statU, const float* __restrict__ statI,
        const float* __restrict__ initU, const float* __restrict__ initI,
        const float* __restrict__ tdW, const float* __restrict__ tdb,
        const float* __restrict__ uWih, const float* __restrict__ uWhh,
        const float* __restrict__ ubih, const float* __restrict__ ubhh,
        const float* __restrict__ iWih, const float* __restrict__ iWhh,
        const float* __restrict__ ibih, const float* __restrict__ ibhh,
        const float* __restrict__ predW,
        float* __restrict__ out) {
    int bx = blockIdx.x;

    if (bx < P1_COPY) {
        copy_range((const float4*)isU, (float4*)(out + OFF_ISNEW_U), 0, N4_ISU, bx, P1_COPY);
        copy_range((const float4*)isI, (float4*)(out + OFF_ISNEW_I), 0, N4_ISI, bx, P1_COPY);
        copy_range((const float4*)dynU, (float4*)(out + OFF_DYN_USER), 0, N4_U, bx, P1_COPY);
        return;
    }
    bx -= P1_COPY;

    if (bx < B) {
        int b = bx;
        int d = threadIdx.x;
        int u = uid[b], p = pid[b], it = iid[b];
        float ti = t_item[b], tu = t_user[b];
        float fu = isU[u], fi = isI[it], fp = isI[p];

        float ue = fu * initU[d] + dynU[(long)u * D + d];
        float ie = fi * initI[d] + dynI[(long)it * D + d];
        float pe = fp * initI[d] + dynI[(long)p * D + d];
        float su = statU[(long)u * D + d];
        float si = statI[(long)it * D + d];
        float ps = statI[(long)p * D + d];

        out[OFF_USER_EMB + b * D + d] = ue;
        out[OFF_ITEM_EMB + b * D + d] = ie;
        out[OFF_TARGET + b * 2 * D + d]     = ie;
        out[OFF_TARGET + b * 2 * D + D + d] = si;

        float proj = ue * (1.f + ti * tdW[d] + tdb[d]);
        // pred X = [proj | pe | ps | su], K=512, fragment layout
        frag_pair_A(g_XpH, g_XpL, b, 0,   d, KFP, proj);
        frag_pair_A(g_XpH, g_XpL, b, 128, d, KFP, pe);
        frag_pair_A(g_XpH, g_XpL, b, 256, d, KFP, ps);
        frag_pair_A(g_XpH, g_XpL, b, 384, d, KFP, su);
        // RNN X layout [x(128)|h(128)|t|pad]: Xu=[ie|ue|ti], Xi=[ue|ie|tu]
        frag_pair_A(g_XuH, g_XuL, b, 0,   d, KFR, ie);
        frag_pair_A(g_XuH, g_XuL, b, 128, d, KFR, ue);
        frag_pair_A(g_XiH, g_XiL, b, 0,   d, KFR, ue);
        frag_pair_A(g_XiH, g_XiL, b, 128, d, KFR, ie);
        if (d < 8) {   // tail pairs k=256..271: (t,0) then zeros
            int k0 = 256 + 2 * d;
            uint32_t uh = 0, ul = 0, ih = 0, il = 0;
            if (d == 0) {
                bf16 h = __float2bfloat16(ti);
                bf16 l = __float2bfloat16(ti - __bfloat162float(h));
                uh = __bfloat16_as_ushort(h); ul = __bfloat16_as_ushort(l);
                h = __float2bfloat16(tu);
                l = __float2bfloat16(tu - __bfloat162float(h));
                ih = __bfloat16_as_ushort(h); il = __bfloat16_as_ushort(l);
            }
            int off = a_off(b, k0, KFR);
            *(uint32_t*)(g_XuH + off) = uh; *(uint32_t*)(g_XuL + off) = ul;
            *(uint32_t*)(g_XiH + off) = ih; *(uint32_t*)(g_XiL + off) = il;
        }
        return;
    }
    bx -= B;

    if (bx < B / 128) {
        int b = bx * 128 + threadIdx.x;
        atomicMax(&g_winner_u[uid[b]], b + 1);
        atomicMax(&g_winner_i[iid[b]], b + 1);
        return;
    }
    bx -= B / 128;

    if (bx < PREP_PRED) {   // pred W: pair per thread
        int pidx = bx * 128 + threadIdx.x;     // 0..65535
        int n = pidx >> 8, k0 = (pidx & 255) * 2;
        float w0 = predW[n * KP + k0], w1 = predW[n * KP + k0 + 1];
        bf16 h0 = __float2bfloat16(w0), h1 = __float2bfloat16(w1);
        bf16 l0 = __float2bfloat16(w0 - __bfloat162float(h0));
        bf16 l1 = __float2bfloat16(w1 - __bfloat162float(h1));
        int off = b_off(n, k0, KFP);
        *(uint32_t*)(g_WpH + off) = (uint32_t)__bfloat16_as_ushort(h0) |
                                    ((uint32_t)__bfloat16_as_ushort(h1) << 16);
        *(uint32_t*)(g_WpL + off) = (uint32_t)__bfloat16_as_ushort(l0) |
                                    ((uint32_t)__bfloat16_as_ushort(l1) << 16);
        return;
    }
    bx -= PREP_PRED;

    {   // RNN W pairs (both cells) + bias
        int pidx = bx * 128 + threadIdx.x;     // 0..17535
        if (pidx < D * (KR / 2)) {
            int n = pidx / (KR / 2), kp = pidx % (KR / 2);
            int k0 = kp * 2;
            float wu[2], wv[2];
            #pragma unroll
            for (int e = 0; e < 2; e++) {
                int k = k0 + e;
                float a = 0.f, c = 0.f;
                if (k < 128)      { a = uWih[n * 129 + k];         c = iWih[n * 129 + k]; }
                else if (k < 256) { a = uWhh[n * 128 + (k - 128)]; c = iWhh[n * 128 + (k - 128)]; }
                else if (k == 256){ a = uWih[n * 129 + 128];       c = iWih[n * 129 + 128]; }
                wu[e] = a; wv[e] = c;
            }
            int off = b_off(n, k0, KFR);
            bf16 h0 = __float2bfloat16(wu[0]), h1 = __float2bfloat16(wu[1]);
            bf16 l0 = __float2bfloat16(wu[0] - __bfloat162float(h0));
            bf16 l1 = __float2bfloat16(wu[1] - __bfloat162float(h1));
            *(uint32_t*)(g_WuH + off) = (uint32_t)__bfloat16_as_ushort(h0) |
                                        ((uint32_t)__bfloat16_as_ushort(h1) << 16);
            *(uint32_t*)(g_WuL + off) = (uint32_t)__bfloat16_as_ushort(l0) |
                                        ((uint32_t)__bfloat16_as_ushort(l1) << 16);
            h0 = __float2bfloat16(wv[0]); h1 = __float2bfloat16(wv[1]);
            l0 = __float2bfloat16(wv[0] - __bfloat162float(h0));
            l1 = __float2bfloat16(wv[1] - __bfloat162float(h1));
            *(uint32_t*)(g_WvH + off) = (uint32_t)__bfloat16_as_ushort(h0) |
                                        ((uint32_t)__bfloat16_as_ushort(h1) << 16);
            *(uint32_t*)(g_WvL + off) = (uint32_t)__bfloat16_as_ushort(l0) |
                                        ((uint32_t)__bfloat16_as_ushort(l1) << 16);
        }
        if (bx == PREP_RNN - 1 && threadIdx.x < D) {
            int i = threadIdx.x;
            g_bu[i] = ubih[i] + ubhh[i];
            g_bi[i] = ibih[i] + ibhh[i];
        }
    }
}
#define P1_GRID (P1_COPY + B + B/128 + PREP_PRED + PREP_RNN)

// ---------------------------------------------------------------------------
// split-precision bf16 HMMA GEMM: CTA 128 thr = 4 warps (2x2), CTA tile 128x64,
// warp tile 64x32; 3 segments (AhBh, AhBl, AlBh) accumulated in fp32.
template <int KF, bool TANH>
__device__ __forceinline__ void mma_gemm(const bf16* __restrict__ AH, const bf16* __restrict__ AL,
                                         const bf16* __restrict__ BH, const bf16* __restrict__ BL,
                                         const float* __restrict__ bias,
                                         float* __restrict__ C, int ldc, int m0, int n0) {
    int tid = threadIdx.x;
    int wid = tid >> 5, lane = tid & 31;
    int m0w = m0 + (wid >> 1) * 64;
    int n0w = n0 + (wid & 1) * 32;
    int mf0 = m0w >> 4, nf0 = n0w >> 3;
    int aslot = lane * 8, bslot = lane * 4;

    float acc[4][4][4];
    #pragma unroll
    for (int i = 0; i < 4; i++)
        #pragma unroll
        for (int j = 0; j < 4; j++)
            #pragma unroll
            for (int q = 0; q < 4; q++) acc[i][j][q] = 0.f;

    #pragma unroll
    for (int seg = 0; seg < 3; seg++) {
        const bf16* Ap = (seg < 2) ? AH : AL;
        const bf16* Bp = (seg == 1) ? BL : BH;
        #pragma unroll 2
        for (int kf = 0; kf < KF; kf++) {
            uint4 a[4];
            uint2 b[4];
            #pragma unroll
            for (int i = 0; i < 4; i++)
                a[i] = *(const uint4*)(Ap + (((mf0 + i) * KF + kf) << 8) + aslot);
            #pragma unroll
            for (int j = 0; j < 4; j++)
                b[j] = *(const uint2*)(Bp + (((nf0 + j) * KF + kf) << 7) + bslot);
            #pragma unroll
            for (int i = 0; i < 4; i++)
                #pragma unroll
                for (int j = 0; j < 4; j++)
                    mma_bf16(acc[i][j], a[i], b[j]);
        }
    }

    int g = lane >> 2, t = lane & 3;
    #pragma unroll
    for (int i = 0; i < 4; i++) {
        #pragma unroll
        for (int j = 0; j < 4; j++) {
            int n = n0w + j * 8 + t * 2;
            float b0 = bias[n], b1 = bias[n + 1];
            float c0 = acc[i][j][0] + b0, c1 = acc[i][j][1] + b1;
            float c2 = acc[i][j][2] + b0, c3 = acc[i][j][3] + b1;
            if (TANH) { c0 = tanhf(c0); c1 = tanhf(c1); c2 = tanhf(c2); c3 = tanhf(c3); }
            int mrow = m0w + i * 16 + g;
            *(float2*)&C[(size_t)mrow * ldc + n]       = make_float2(c0, c1);
            *(float2*)&C[(size_t)(mrow + 8) * ldc + n] = make_float2(c2, c3);
        }
    }
}

// ---------------------------------------------------------------------------
// phase2: [copy dynI | pred MMA (128 CTAs) | RNN MMAs (128 CTAs)]
__global__ void __launch_bounds__(128) phase2_kernel(
        const float* __restrict__ dynI,
        const float* __restrict__ predb,
        float* __restrict__ out) {
    int bx = blockIdx.x;

    if (bx < P2_COPY) {
        copy_range((const float4*)dynI, (float4*)(out + OFF_DYN_ITEM), 0, N4_I, bx, P2_COPY);
        return;
    }
    bx -= P2_COPY;

    if (bx < 128) {      // pred: 32 M-tiles x 4 N-tiles
        int m0 = (bx & 31) * 128, n0 = (bx >> 5) * 64;
        mma_gemm<KFP, false>(g_XpH, g_XpL, g_WpH, g_WpL, predb,
                             out + OFF_PRED, 256, m0, n0);
        return;
    }
    bx -= 128;

    if (bx < 64) {       // RNN user: 32 M-tiles x 2 N-tiles
        int m0 = (bx & 31) * 128, n0 = (bx >> 5) * 64;
        mma_gemm<KFR, true>(g_XuH, g_XuL, g_WuH, g_WuL, g_bu,
                            out + OFF_UPD_USER, 128, m0, n0);
        return;
    }
    bx -= 64;

    {                    // RNN item
        int m0 = (bx & 31) * 128, n0 = (bx >> 5) * 64;
        mma_gemm<KFR, true>(g_XiH, g_XiL, g_WvH, g_WvL, g_bi,
                            out + OFF_UPD_ITEM, 128, m0, n0);
    }
}
#define P2_GRID (P2_COPY + 128 + 64 + 64)

// ---------------------------------------------------------------------------
// patch winner rows, zero is_new for batch ids, reset consumed winner entries
__global__ void scatter_kernel(const int* __restrict__ uid, const int* __restrict__ iid,
                               float* __restrict__ out) {
    int gw = blockIdx.x * 8 + (threadIdx.x >> 5);
    int lane = threadIdx.x & 31;
    if (gw < B) {
        int id = uid[gw];
        if (lane == 0) out[OFF_ISNEW_U + id] = 0.f;
        if (g_winner_u[id] == gw + 1) {
            float4 v = *(const float4*)(out + OFF_UPD_USER + (long)gw * D + lane * 4);
            *(float4*)(out + OFF_DYN_USER + (long)id * D + lane * 4) = v;
            if (lane == 0) g_winner_u[id] = 0;
        }
    } else {
        int b = gw - B;
        if (b < B) {
            int id = iid[b];
            if (lane == 0) out[OFF_ISNEW_I + id] = 0.f;
            if (g_winner_i[id] == b + 1) {
                float4 v = *(const float4*)(out + OFF_UPD_ITEM + (long)b * D + lane * 4);
                *(float4*)(out + OFF_DYN_ITEM + (long)id * D + lane * 4) = v;
                if (lane == 0) g_winner_i[id] = 0;
            }
        }
    }
}

// ---------------------------------------------------------------------------
extern "C" void kernel_launch(void* const* d_in, const int* in_sizes, int n_in,
                              void* d_out, int out_size) {
    const int*   uid   = (const int*)d_in[0];
    const int*   pid   = (const int*)d_in[1];
    const int*   iid   = (const int*)d_in[2];
    const float* tItem = (const float*)d_in[3];
    const float* tUser = (const float*)d_in[4];
    const float* dynU  = (const float*)d_in[5];
    const float* dynI  = (const float*)d_in[6];
    const float* isU   = (const float*)d_in[7];
    const float* isI   = (const float*)d_in[8];
    const float* statU = (const float*)d_in[9];
    const float* statI = (const float*)d_in[10];
    const float* initU = (const float*)d_in[11];
    const float* initI = (const float*)d_in[12];
    const float* uWih  = (const float*)d_in[13];
    const float* uWhh  = (const float*)d_in[14];
    const float* ubih  = (const float*)d_in[15];
    const float* ubhh  = (const float*)d_in[16];
    const float* iWih  = (const float*)d_in[17];
    const float* iWhh  = (const float*)d_in[18];
    const float* ibih  = (const float*)d_in[19];
    const float* ibhh  = (const float*)d_in[20];
    const float* predW = (const float*)d_in[21];
    const float* predb = (const float*)d_in[22];
    const float* tdW   = (const float*)d_in[23];
    const float* tdb   = (const float*)d_in[24];
    float* out = (float*)d_out;

    phase1_kernel<<<P1_GRID, 128>>>(uid, pid, iid, tItem, tUser, dynU, dynI,
                                    isU, isI, statU, statI, initU, initI,
                                    tdW, tdb, uWih, uWhh, ubih, ubhh,
                                    iWih, iWhh, ibih, ibhh, predW, out);
    phase2_kernel<<<P2_GRID, 128>>>(dynI, predb, out);
    scatter_kernel<<<(2 * B) / 8, 256>>>(uid, iid, out);
}

// round 12
// speedup vs baseline: 1.2799x; 1.2551x over previous
#include <cuda_runtime.h>
#include <cuda_bf16.h>
#include <math.h>
#include <stdint.h>

#define NU 200000
#define NI 200000
#define D  128
#define B  4096
#define KP  512     // pred K
#define KFP 32      // pred K frags (K/16)
#define KR  272     // RNN K: [x(128) | h(128) | t(1) | pad(15)]
#define KFR 17      // RNN K frags

// ---- output layout (flattened tuple, row-major) ----
#define OFF_PRED       0
#define OFF_TARGET     (B*2*D)
#define OFF_UPD_USER   (OFF_TARGET + B*2*D)
#define OFF_USER_EMB   (OFF_UPD_USER + B*D)
#define OFF_UPD_ITEM   (OFF_USER_EMB + B*D)
#define OFF_ITEM_EMB   (OFF_UPD_ITEM + B*D)
#define OFF_DYN_USER   (OFF_ITEM_EMB + B*D)
#define OFF_DYN_ITEM   (OFF_DYN_USER + NU*D)
#define OFF_ISNEW_U    (OFF_DYN_ITEM + NI*D)
#define OFF_ISNEW_I    (OFF_ISNEW_U + NU)

typedef __nv_bfloat16 bf16;

// ---- device scratch: operands in m16n8k16 FRAGMENT layout, hi/lo bf16 ----
__device__ __align__(16) bf16 g_XpH[B * KP];
__device__ __align__(16) bf16 g_XpL[B * KP];
__device__ __align__(16) bf16 g_XuH[B * KR];
__device__ __align__(16) bf16 g_XuL[B * KR];
__device__ __align__(16) bf16 g_XiH[B * KR];
__device__ __align__(16) bf16 g_XiL[B * KR];
__device__ __align__(16) bf16 g_WpH[256 * KP];
__device__ __align__(16) bf16 g_WpL[256 * KP];
__device__ __align__(16) bf16 g_WuH[D * KR];
__device__ __align__(16) bf16 g_WuL[D * KR];
__device__ __align__(16) bf16 g_WvH[D * KR];
__device__ __align__(16) bf16 g_WvL[D * KR];
__device__ float g_bu[D];
__device__ float g_bi[D];
// winner sentinel: 0 = none, else b+1. Zero-init at load; scatter resets.
__device__ int g_winner_u[NU];
__device__ int g_winner_i[NI];

// m16n8k16 A-fragment offset (bf16 units) for even k (pair-aligned)
__device__ __forceinline__ int a_off(int m, int k0, int KF) {
    int mf = m >> 4, r = m & 15, g = r & 7, h = r >> 3;
    int kf = k0 >> 4, kl = k0 & 15, t = (kl >> 1) & 3, reg = h + 2 * (kl >> 3);
    return ((mf * KF + kf) << 8) + (((g << 2) + t) << 3) + reg * 2;
}
// B-fragment offset
__device__ __forceinline__ int b_off(int n, int k0, int KF) {
    int nf = n >> 3, g = n & 7;
    int kf = k0 >> 4, kl = k0 & 15, t = (kl >> 1) & 3, reg = kl >> 3;
    return ((nf * KF + kf) << 7) + (((g << 2) + t) << 2) + reg * 2;
}

__device__ __forceinline__ void mma_bf16(float* c, uint4 a, uint2 b) {
    asm volatile(
        "mma.sync.aligned.m16n8k16.row.col.f32.bf16.bf16.f32 "
        "{%0,%1,%2,%3},{%4,%5,%6,%7},{%8,%9},{%0,%1,%2,%3};"
        : "+f"(c[0]), "+f"(c[1]), "+f"(c[2]), "+f"(c[3])
        : "r"(a.x), "r"(a.y), "r"(a.z), "r"(a.w), "r"(b.x), "r"(b.y));
}

// ---- copy machinery: MLP=8 + streaming hints (evict-first both sides) ----
#define N4_U    (NU * D / 4)
#define N4_I    (NI * D / 4)
#define N4_ISU  (NU / 4)
#define N4_ISI  (NI / 4)
#define P1_COPY 1536

template <int T>
__device__ __forceinline__ void copy_range(const float4* __restrict__ src,
                                           float4* __restrict__ dst,
                                           int lo, int hi, int cta, int ncta) {
    int stride = ncta * T;
    int i = lo + cta * T + (int)threadIdx.x;
    for (; i + 7 * stride < hi; i += 8 * stride) {
        float4 v0 = __ldcs(src + i);
        float4 v1 = __ldcs(src + i + stride);
        float4 v2 = __ldcs(src + i + 2 * stride);
        float4 v3 = __ldcs(src + i + 3 * stride);
        float4 v4 = __ldcs(src + i + 4 * stride);
        float4 v5 = __ldcs(src + i + 5 * stride);
        float4 v6 = __ldcs(src + i + 6 * stride);
        float4 v7 = __ldcs(src + i + 7 * stride);
        __stcs(dst + i,              v0); __stcs(dst + i + stride,     v1);
        __stcs(dst + i + 2 * stride, v2); __stcs(dst + i + 3 * stride, v3);
        __stcs(dst + i + 4 * stride, v4); __stcs(dst + i + 5 * stride, v5);
        __stcs(dst + i + 6 * stride, v6); __stcs(dst + i + 7 * stride, v7);
    }
    for (; i < hi; i += stride) __stcs(dst + i, __ldcs(src + i));
}

// split v into hi/lo bf16, pack with lane-partner (d^1) and store pair (even d)
__device__ __forceinline__ void frag_pair_A(bf16* Hd, bf16* Ld, int m, int kbase,
                                            int d, int KF, float v) {
    bf16 h = __float2bfloat16(v);
    bf16 l = __float2bfloat16(v - __bfloat162float(h));
    uint32_t hu = __bfloat16_as_ushort(h), lu = __bfloat16_as_ushort(l);
    uint32_t ph = __shfl_xor_sync(0xffffffffu, hu, 1);
    uint32_t pl = __shfl_xor_sync(0xffffffffu, lu, 1);
    if (!(d & 1)) {
        int off = a_off(m, kbase + d, KF);
        *(uint32_t*)(Hd + off) = hu | (ph << 16);
        *(uint32_t*)(Ld + off) = lu | (pl << 16);
    }
}

// ---------------------------------------------------------------------------
// phase1: [copy dynU+flags | gather (frag-layout X) | winner | prep (frag W)]
#define PREP_PRED 512        // 65536 pred-W pairs / 128
#define PREP_RNN  137        // 17408 rnn pairs / 128 + bias block
__global__ void __launch_bounds__(128) phase1_kernel(
        const int* __restrict__ uid, const int* __restrict__ pid,
        const int* __restrict__ iid,
        const float* __restrict__ t_item, const float* __restrict__ t_user,
        const float* __restrict__ dynU, const float* __restrict__ dynI,
        const float* __restrict__ isU, const float* __restrict__ isI,
        const float* __restrict__ statU, const float* __restrict__ statI,
        const float* __restrict__ initU, const float* __restrict__ initI,
        const float* __restrict__ tdW, const float* __restrict__ tdb,
        const float* __restrict__ uWih, const float* __restrict__ uWhh,
        const float* __restrict__ ubih, const float* __restrict__ ubhh,
        const float* __restrict__ iWih, const float* __restrict__ iWhh,
        const float* __restrict__ ibih, const float* __restrict__ ibhh,
        const float* __restrict__ predW,
        float* __restrict__ out) {
    int bx = blockIdx.x;

    if (bx < P1_COPY) {
        copy_range<128>((const float4*)isU, (float4*)(out + OFF_ISNEW_U), 0, N4_ISU, bx, P1_COPY);
        copy_range<128>((const float4*)isI, (float4*)(out + OFF_ISNEW_I), 0, N4_ISI, bx, P1_COPY);
        copy_range<128>((const float4*)dynU, (float4*)(out + OFF_DYN_USER), 0, N4_U, bx, P1_COPY);
        return;
    }
    bx -= P1_COPY;

    if (bx < B) {
        int b = bx;
        int d = threadIdx.x;
        int u = uid[b], p = pid[b], it = iid[b];
        float ti = t_item[b], tu = t_user[b];
        float fu = isU[u], fi = isI[it], fp = isI[p];

        float ue = fu * initU[d] + dynU[(long)u * D + d];
        float ie = fi * initI[d] + dynI[(long)it * D + d];
        float pe = fp * initI[d] + dynI[(long)p * D + d];
        float su = statU[(long)u * D + d];
        float si = statI[(long)it * D + d];
        float ps = statI[(long)p * D + d];

        out[OFF_USER_EMB + b * D + d] = ue;
        out[OFF_ITEM_EMB + b * D + d] = ie;
        out[OFF_TARGET + b * 2 * D + d]     = ie;
        out[OFF_TARGET + b * 2 * D + D + d] = si;

        float proj = ue * (1.f + ti * tdW[d] + tdb[d]);
        frag_pair_A(g_XpH, g_XpL, b, 0,   d, KFP, proj);
        frag_pair_A(g_XpH, g_XpL, b, 128, d, KFP, pe);
        frag_pair_A(g_XpH, g_XpL, b, 256, d, KFP, ps);
        frag_pair_A(g_XpH, g_XpL, b, 384, d, KFP, su);
        frag_pair_A(g_XuH, g_XuL, b, 0,   d, KFR, ie);
        frag_pair_A(g_XuH, g_XuL, b, 128, d, KFR, ue);
        frag_pair_A(g_XiH, g_XiL, b, 0,   d, KFR, ue);
        frag_pair_A(g_XiH, g_XiL, b, 128, d, KFR, ie);
        if (d < 8) {   // tail pairs k=256..271: (t,0) then zeros
            int k0 = 256 + 2 * d;
            uint32_t uh = 0, ul = 0, ih = 0, il = 0;
            if (d == 0) {
                bf16 h = __float2bfloat16(ti);
                bf16 l = __float2bfloat16(ti - __bfloat162float(h));
                uh = __bfloat16_as_ushort(h); ul = __bfloat16_as_ushort(l);
                h = __float2bfloat16(tu);
                l = __float2bfloat16(tu - __bfloat162float(h));
                ih = __bfloat16_as_ushort(h); il = __bfloat16_as_ushort(l);
            }
            int off = a_off(b, k0, KFR);
            *(uint32_t*)(g_XuH + off) = uh; *(uint32_t*)(g_XuL + off) = ul;
            *(uint32_t*)(g_XiH + off) = ih; *(uint32_t*)(g_XiL + off) = il;
        }
        return;
    }
    bx -= B;

    if (bx < B / 128) {
        int b = bx * 128 + threadIdx.x;
        atomicMax(&g_winner_u[uid[b]], b + 1);
        atomicMax(&g_winner_i[iid[b]], b + 1);
        return;
    }
    bx -= B / 128;

    if (bx < PREP_PRED) {   // pred W: pair per thread
        int pidx = bx * 128 + threadIdx.x;
        int n = pidx >> 8, k0 = (pidx & 255) * 2;
        float w0 = predW[n * KP + k0], w1 = predW[n * KP + k0 + 1];
        bf16 h0 = __float2bfloat16(w0), h1 = __float2bfloat16(w1);
        bf16 l0 = __float2bfloat16(w0 - __bfloat162float(h0));
        bf16 l1 = __float2bfloat16(w1 - __bfloat162float(h1));
        int off = b_off(n, k0, KFP);
        *(uint32_t*)(g_WpH + off) = (uint32_t)__bfloat16_as_ushort(h0) |
                                    ((uint32_t)__bfloat16_as_ushort(h1) << 16);
        *(uint32_t*)(g_WpL + off) = (uint32_t)__bfloat16_as_ushort(l0) |
                                    ((uint32_t)__bfloat16_as_ushort(l1) << 16);
        return;
    }
    bx -= PREP_PRED;

    {   // RNN W pairs (both cells) + bias
        int pidx = bx * 128 + threadIdx.x;
        if (pidx < D * (KR / 2)) {
            int n = pidx / (KR / 2), kp = pidx % (KR / 2);
            int k0 = kp * 2;
            float wu[2], wv[2];
            #pragma unroll
            for (int e = 0; e < 2; e++) {
                int k = k0 + e;
                float a = 0.f, c = 0.f;
                if (k < 128)      { a = uWih[n * 129 + k];         c = iWih[n * 129 + k]; }
                else if (k < 256) { a = uWhh[n * 128 + (k - 128)]; c = iWhh[n * 128 + (k - 128)]; }
                else if (k == 256){ a = uWih[n * 129 + 128];       c = iWih[n * 129 + 128]; }
                wu[e] = a; wv[e] = c;
            }
            int off = b_off(n, k0, KFR);
            bf16 h0 = __float2bfloat16(wu[0]), h1 = __float2bfloat16(wu[1]);
            bf16 l0 = __float2bfloat16(wu[0] - __bfloat162float(h0));
            bf16 l1 = __float2bfloat16(wu[1] - __bfloat162float(h1));
            *(uint32_t*)(g_WuH + off) = (uint32_t)__bfloat16_as_ushort(h0) |
                                        ((uint32_t)__bfloat16_as_ushort(h1) << 16);
            *(uint32_t*)(g_WuL + off) = (uint32_t)__bfloat16_as_ushort(l0) |
                                        ((uint32_t)__bfloat16_as_ushort(l1) << 16);
            h0 = __float2bfloat16(wv[0]); h1 = __float2bfloat16(wv[1]);
            l0 = __float2bfloat16(wv[0] - __bfloat162float(h0));
            l1 = __float2bfloat16(wv[1] - __bfloat162float(h1));
            *(uint32_t*)(g_WvH + off) = (uint32_t)__bfloat16_as_ushort(h0) |
                                        ((uint32_t)__bfloat16_as_ushort(h1) << 16);
            *(uint32_t*)(g_WvL + off) = (uint32_t)__bfloat16_as_ushort(l0) |
                                        ((uint32_t)__bfloat16_as_ushort(l1) << 16);
        }
        if (bx == PREP_RNN - 1 && threadIdx.x < D) {
            int i = threadIdx.x;
            g_bu[i] = ubih[i] + ubhh[i];
            g_bi[i] = ibih[i] + ibhh[i];
        }
    }
}
#define P1_GRID (P1_COPY + B + B/128 + PREP_PRED + PREP_RNN)

// ---------------------------------------------------------------------------
// split-precision bf16 HMMA GEMM: 256-thr CTA = 8 warps (2M x 4N),
// CTA tile 128x128, warp tile 64x32; 3 segments accumulated in fp32.
template <int KF, bool TANH>
__device__ __forceinline__ void mma_gemm(const bf16* __restrict__ AH, const bf16* __restrict__ AL,
                                         const bf16* __restrict__ BH, const bf16* __restrict__ BL,
                                         const float* __restrict__ bias,
                                         float* __restrict__ C, int ldc, int m0, int n0) {
    int tid = threadIdx.x;
    int wid = tid >> 5, lane = tid & 31;
    int m0w = m0 + (wid >> 2) * 64;
    int n0w = n0 + (wid & 3) * 32;
    int mf0 = m0w >> 4, nf0 = n0w >> 3;
    int aslot = lane * 8, bslot = lane * 4;

    float acc[4][4][4];
    #pragma unroll
    for (int i = 0; i < 4; i++)
        #pragma unroll
        for (int j = 0; j < 4; j++)
            #pragma unroll
            for (int q = 0; q < 4; q++) acc[i][j][q] = 0.f;

    #pragma unroll
    for (int seg = 0; seg < 3; seg++) {
        const bf16* Ap = (seg < 2) ? AH : AL;
        const bf16* Bp = (seg == 1) ? BL : BH;
        #pragma unroll 2
        for (int kf = 0; kf < KF; kf++) {
            uint4 a[4];
            uint2 b[4];
            #pragma unroll
            for (int i = 0; i < 4; i++)
                a[i] = *(const uint4*)(Ap + (((mf0 + i) * KF + kf) << 8) + aslot);
            #pragma unroll
            for (int j = 0; j < 4; j++)
                b[j] = *(const uint2*)(Bp + (((nf0 + j) * KF + kf) << 7) + bslot);
            #pragma unroll
            for (int i = 0; i < 4; i++)
                #pragma unroll
                for (int j = 0; j < 4; j++)
                    mma_bf16(acc[i][j], a[i], b[j]);
        }
    }

    int g = lane >> 2, t = lane & 3;
    #pragma unroll
    for (int i = 0; i < 4; i++) {
        #pragma unroll
        for (int j = 0; j < 4; j++) {
            int n = n0w + j * 8 + t * 2;
            float b0 = bias[n], b1 = bias[n + 1];
            float c0 = acc[i][j][0] + b0, c1 = acc[i][j][1] + b1;
            float c2 = acc[i][j][2] + b0, c3 = acc[i][j][3] + b1;
            if (TANH) { c0 = tanhf(c0); c1 = tanhf(c1); c2 = tanhf(c2); c3 = tanhf(c3); }
            int mrow = m0w + i * 16 + g;
            *(float2*)&C[(size_t)mrow * ldc + n]       = make_float2(c0, c1);
            *(float2*)&C[(size_t)(mrow + 8) * ldc + n] = make_float2(c2, c3);
        }
    }
}

// ---------------------------------------------------------------------------
// phase2, 256 thr/CTA: [pred MMA (64) | RNN MMAs (64) | copy dynI (768)]
// MMA CTAs first: they run in wave 1 while X/W are hot in L2.
#define P2_COPY 768
__global__ void __launch_bounds__(256) phase2_kernel(
        const float* __restrict__ dynI,
        const float* __restrict__ predb,
        float* __restrict__ out) {
    int bx = blockIdx.x;

    if (bx < 64) {       // pred: 32 M-tiles x 2 N-tiles (128x128 CTA tile)
        int m0 = (bx & 31) * 128, n0 = (bx >> 5) * 128;
        mma_gemm<KFP, false>(g_XpH, g_XpL, g_WpH, g_WpL, predb,
                             out + OFF_PRED, 256, m0, n0);
        return;
    }
    bx -= 64;

    if (bx < 32) {       // RNN user: 32 M-tiles, N=128 single tile
        mma_gemm<KFR, true>(g_XuH, g_XuL, g_WuH, g_WuL, g_bu,
                            out + OFF_UPD_USER, 128, bx * 128, 0);
        return;
    }
    bx -= 32;

    if (bx < 32) {       // RNN item
        mma_gemm<KFR, true>(g_XiH, g_XiL, g_WvH, g_WvL, g_bi,
                            out + OFF_UPD_ITEM, 128, bx * 128, 0);
        return;
    }
    bx -= 32;

    copy_range<256>((const float4*)dynI, (float4*)(out + OFF_DYN_ITEM), 0, N4_I, bx, P2_COPY);
}
#define P2_GRID (64 + 32 + 32 + P2_COPY)

// ---------------------------------------------------------------------------
// patch winner rows, zero is_new for batch ids, reset consumed winner entries
__global__ void scatter_kernel(const int* __restrict__ uid, const int* __restrict__ iid,
                               float* __restrict__ out) {
    int gw = blockIdx.x * 8 + (threadIdx.x >> 5);
    int lane = threadIdx.x & 31;
    if (gw < B) {
        int id = uid[gw];
        if (lane == 0) out[OFF_ISNEW_U + id] = 0.f;
        if (g_winner_u[id] == gw + 1) {
            float4 v = *(const float4*)(out + OFF_UPD_USER + (long)gw * D + lane * 4);
            *(float4*)(out + OFF_DYN_USER + (long)id * D + lane * 4) = v;
            if (lane == 0) g_winner_u[id] = 0;
        }
    } else {
        int b = gw - B;
        if (b < B) {
            int id = iid[b];
            if (lane == 0) out[OFF_ISNEW_I + id] = 0.f;
            if (g_winner_i[id] == b + 1) {
                float4 v = *(const float4*)(out + OFF_UPD_ITEM + (long)b * D + lane * 4);
                *(float4*)(out + OFF_DYN_ITEM + (long)id * D + lane * 4) = v;
                if (lane == 0) g_winner_i[id] = 0;
            }
        }
    }
}

// ---------------------------------------------------------------------------
extern "C" void kernel_launch(void* const* d_in, const int* in_sizes, int n_in,
                              void* d_out, int out_size) {
    const int*   uid   = (const int*)d_in[0];
    const int*   pid   = (const int*)d_in[1];
    const int*   iid   = (const int*)d_in[2];
    const float* tItem = (const float*)d_in[3];
    const float* tUser = (const float*)d_in[4];
    const float* dynU  = (const float*)d_in[5];
    const float* dynI  = (const float*)d_in[6];
    const float* isU   = (const float*)d_in[7];
    const float* isI   = (const float*)d_in[8];
    const float* statU = (const float*)d_in[9];
    const float* statI = (const float*)d_in[10];
    const float* initU = (const float*)d_in[11];
    const float* initI = (const float*)d_in[12];
    const float* uWih  = (const float*)d_in[13];
    const float* uWhh  = (const float*)d_in[14];
    const float* ubih  = (const float*)d_in[15];
    const float* ubhh  = (const float*)d_in[16];
    const float* iWih  = (const float*)d_in[17];
    const float* iWhh  = (const float*)d_in[18];
    const float* ibih  = (const float*)d_in[19];
    const float* ibhh  = (const float*)d_in[20];
    const float* predW = (const float*)d_in[21];
    const float* predb = (const float*)d_in[22];
    const float* tdW   = (const float*)d_in[23];
    const float* tdb   = (const float*)d_in[24];
    float* out = (float*)d_out;

    phase1_kernel<<<P1_GRID, 128>>>(uid, pid, iid, tItem, tUser, dynU, dynI,
                                    isU, isI, statU, statI, initU, initI,
                                    tdW, tdb, uWih, uWhh, ubih, ubhh,
                                    iWih, iWhh, ibih, ibhh, predW, out);
    phase2_kernel<<<P2_GRID, 256>>>(dynI, predb, out);
    scatter_kernel<<<(2 * B) / 8, 256>>>(uid, iid, out);
}